// round 14
// baseline (speedup 1.0000x reference)
#include <cuda_runtime.h>

// Problem constants (fixed by the dataset)
#define IMG    144
#define B_     4
#define N_     1296          // tokens per batch
#define NP_    36
#define JTILES 18
#define JT     72            // N_ / JTILES (divisible by 4)
#define JG     18            // JT/4 key groups
#define ROWTILES 6           // 6 * 216 = 1296 rows
#define RT_ROWS 216          // rows per block = QT * 2
#define QT     108           // active threads per block (each owns 2 rows)
#define ATTN_BLOCKS (B_ * ROWTILES * JTILES)   // 432
#define MAXBLOCKS 27

#define LOG2E 1.4426950408889634f
// score scale in u8 units: arg = (2*dot - |u_j|^2 - |u_i|^2) * S2  (xmax cancels)
#define S2 (1.4426950408889634f / (16.0f * 65025.0f))

// Scratch: integer partials [b][jt][d(17)][N_] (~6.4MB, L2-resident); block
// maxes; per-(b,rowtile) counters (monotone across graph replays: each launch
// adds exactly JTILES -> old%JTILES==JTILES-1 marks last arrival; no reset).
__device__ unsigned g_part[B_ * JTILES * 17 * N_];
__device__ float    g_bmax[MAXBLOCKS];
__device__ unsigned g_cnt[B_ * ROWTILES];

__device__ __forceinline__ float ex2_approx(float a) {
    float r;
    asm("ex2.approx.ftz.f32 %0, %1;" : "=f"(r) : "f"(a));
    return r;
}
__device__ __forceinline__ unsigned dp4a_u(unsigned a, unsigned b, unsigned c) {
    unsigned r;
    asm("dp4a.u32.u32 %0, %1, %2, %3;" : "=r"(r) : "r"(a), "r"(b), "r"(c));
    return r;
}
__device__ __forceinline__ unsigned prmt(unsigned a, unsigned b, unsigned sel) {
    unsigned r;
    asm("prmt.b32 %0, %1, %2, %3;" : "=r"(r) : "r"(a), "r"(b), "r"(sel));
    return r;
}
// quantize a float4 (values in [0,xmax]) to packed u8x4 with scale r255=255/xmax
__device__ __forceinline__ unsigned quant4(float4 v, float r255) {
    unsigned q0 = (unsigned)__float2int_rn(v.x * r255);
    unsigned q1 = (unsigned)__float2int_rn(v.y * r255);
    unsigned q2 = (unsigned)__float2int_rn(v.z * r255);
    unsigned q3 = (unsigned)__float2int_rn(v.w * r255);
    return q0 | (q1 << 8) | (q2 << 16) | (q3 << 24);
}

// ---------------- kernel 0: per-block max (values >= 0) ----------------
__global__ void k_max(const float* __restrict__ x) {
    const float4* xv = reinterpret_cast<const float4*>(x);
    int base = blockIdx.x * 768 + threadIdx.x;   // 27*768 = 20736 float4 exactly
    float4 v0 = xv[base];
    float4 v1 = xv[base + 256];
    float4 v2 = xv[base + 512];
    float m = fmaxf(fmaxf(fmaxf(v0.x, v0.y), fmaxf(v0.z, v0.w)),
              fmaxf(fmaxf(fmaxf(v1.x, v1.y), fmaxf(v1.z, v1.w)),
                    fmaxf(fmaxf(v2.x, v2.y), fmaxf(v2.z, v2.w))));
    #pragma unroll
    for (int o = 16; o > 0; o >>= 1)
        m = fmaxf(m, __shfl_xor_sync(0xFFFFFFFFu, m, o));
    __shared__ float sm[8];
    int warp = threadIdx.x >> 5, lane = threadIdx.x & 31;
    if (lane == 0) sm[warp] = m;
    __syncthreads();
    if (warp == 0) {
        m = sm[lane & 7];
        #pragma unroll
        for (int o = 4; o > 0; o >>= 1)
            m = fmaxf(m, __shfl_xor_sync(0xFFFFFFFFu, m, o));
        if (lane == 0) g_bmax[blockIdx.x] = m;
    }
}

// ---------------- kernel 1: 2-query-per-thread integer attention ------------
// Every LDS.128 of key data now serves TWO query rows (the smem crossbar at
// 4cyc/LDS SM-wide was the measured binder). Scores: u8 dp4a dots + magic-bias
// int->float + ex2 (MUFU). Weights wq = round(w * 255*2^ci) stay in [94,255]
// (row factor cancels in the ratio). AV + denom via dp4a on a dim-transposed
// u8 tile. Last block per (b,rowtile) combines partials -> output.
__global__ void __launch_bounds__(128) k_attn(const float* __restrict__ x,
                                              float* __restrict__ out) {
    __shared__ unsigned s_q[JT * 4];    // key-major u8x4 (for Q.K dots)
    __shared__ unsigned s_qT[JG * 16];  // dim-major: word(g,d) = {u_{4g+k}[d]}
    __shared__ float    s_cj[JT];
    __shared__ float    s_red[4];
    __shared__ int      s_last;

    int bid = blockIdx.x;
    int jt  = bid % JTILES;
    int rt  = (bid / JTILES) % ROWTILES;
    int b   = bid / (JTILES * ROWTILES);
    int tid = threadIdx.x;
    int lane = tid & 31, warp = tid >> 5;

    const float* xb = x + b * (N_ * 16);
    const float twoS2 = 2.0f * S2;

    // reduce the 27 block maxes (tiny, L2-hit broadcasts)
    float m = (tid < MAXBLOCKS) ? g_bmax[tid] : 0.0f;
    #pragma unroll
    for (int o = 16; o > 0; o >>= 1)
        m = fmaxf(m, __shfl_xor_sync(0xFFFFFFFFu, m, o));
    if (lane == 0) s_red[warp] = m;
    __syncthreads();
    float xmax = fmaxf(fmaxf(s_red[0], s_red[1]), fmaxf(s_red[2], s_red[3]));
    float r255 = 255.0f / xmax;

    // fill this j-tile: quantize + byte-scatter transposed copy (JT*4=288 w)
    {
        const float4* src = reinterpret_cast<const float4*>(xb + jt * (JT * 16));
        unsigned char* bt = reinterpret_cast<unsigned char*>(s_qT);
        for (int k = tid; k < JT * 4; k += 128) {   // k: float4 index; key j=k>>2
            float4 v = src[k];
            unsigned q = quant4(v, r255);
            s_q[k] = q;
            int j = k >> 2, p = k & 3;              // dims 4p..4p+3
            int g = j >> 2, ln = j & 3;
            int w0 = (g * 16 + 4 * p) * 4 + ln;
            bt[w0]      = (unsigned char)(q       & 255);
            bt[w0 + 4]  = (unsigned char)((q >> 8) & 255);
            bt[w0 + 8]  = (unsigned char)((q >> 16) & 255);
            bt[w0 + 12] = (unsigned char)(q >> 24);
        }
    }
    __syncthreads();

    // per-key constant: c_j = -|u_j|^2 * S2 - 2^23 * twoS2 (magic-bias fold)
    if (tid < JT) {
        const unsigned* kq = s_q + tid * 4;
        unsigned qq = dp4a_u(kq[0], kq[0],
                      dp4a_u(kq[1], kq[1],
                      dp4a_u(kq[2], kq[2],
                      dp4a_u(kq[3], kq[3], 0u))));
        s_cj[tid] = fmaf(-8388608.0f, twoS2, -(float)qq * S2);
    }
    __syncthreads();

    bool active = (tid < QT);
    int i1 = rt * RT_ROWS + tid;        // rows rt*216 .. rt*216+107
    int i2 = i1 + QT;                   // rows rt*216+108 .. rt*216+215

    if (active) {
        // two quantized queries
        const float4* t1 = reinterpret_cast<const float4*>(xb + i1 * 16);
        const float4* t2 = reinterpret_cast<const float4*>(xb + i2 * 16);
        float4 a0 = t1[0], a1 = t1[1], a2 = t1[2], a3 = t1[3];
        float4 c0 = t2[0], c1 = t2[1], c2 = t2[2], c3 = t2[3];
        unsigned q1v[4], q2v[4];
        q1v[0] = quant4(a0, r255); q1v[1] = quant4(a1, r255);
        q1v[2] = quant4(a2, r255); q1v[3] = quant4(a3, r255);
        q2v[0] = quant4(c0, r255); q2v[1] = quant4(c1, r255);
        q2v[2] = quant4(c2, r255); q2v[3] = quant4(c3, r255);

        // per-row weight scales R = 255 * 2^(-|u_i|^2 * S2)
        unsigned s1 = dp4a_u(q1v[0], q1v[0], dp4a_u(q1v[1], q1v[1],
                     dp4a_u(q1v[2], q1v[2], dp4a_u(q1v[3], q1v[3], 0u))));
        unsigned s2 = dp4a_u(q2v[0], q2v[0], dp4a_u(q2v[1], q2v[1],
                     dp4a_u(q2v[2], q2v[2], dp4a_u(q2v[3], q2v[3], 0u))));
        float R1 = 255.0f * ex2_approx(-(float)s1 * S2);
        float R2 = 255.0f * ex2_approx(-(float)s2 * S2);

        unsigned av1[16], av2[16];
        #pragma unroll
        for (int d = 0; d < 16; ++d) { av1[d] = 0u; av2[d] = 0u; }
        unsigned ds1 = 0u, ds2 = 0u;

        const uint4* sq4  = reinterpret_cast<const uint4*>(s_q);
        const uint4* sqT4 = reinterpret_cast<const uint4*>(s_qT);

        #pragma unroll 2
        for (int g = 0; g < JG; ++g) {
            uint4 k0 = sq4[4 * g + 0];
            uint4 k1 = sq4[4 * g + 1];
            uint4 k2 = sq4[4 * g + 2];
            uint4 k3 = sq4[4 * g + 3];

            // 8 dots (4 keys x 2 queries)
            unsigned dA0 = dp4a_u(q1v[0], k0.x, dp4a_u(q1v[1], k0.y,
                           dp4a_u(q1v[2], k0.z, dp4a_u(q1v[3], k0.w, 0u))));
            unsigned dA1 = dp4a_u(q1v[0], k1.x, dp4a_u(q1v[1], k1.y,
                           dp4a_u(q1v[2], k1.z, dp4a_u(q1v[3], k1.w, 0u))));
            unsigned dA2 = dp4a_u(q1v[0], k2.x, dp4a_u(q1v[1], k2.y,
                           dp4a_u(q1v[2], k2.z, dp4a_u(q1v[3], k2.w, 0u))));
            unsigned dA3 = dp4a_u(q1v[0], k3.x, dp4a_u(q1v[1], k3.y,
                           dp4a_u(q1v[2], k3.z, dp4a_u(q1v[3], k3.w, 0u))));
            unsigned dB0 = dp4a_u(q2v[0], k0.x, dp4a_u(q2v[1], k0.y,
                           dp4a_u(q2v[2], k0.z, dp4a_u(q2v[3], k0.w, 0u))));
            unsigned dB1 = dp4a_u(q2v[0], k1.x, dp4a_u(q2v[1], k1.y,
                           dp4a_u(q2v[2], k1.z, dp4a_u(q2v[3], k1.w, 0u))));
            unsigned dB2 = dp4a_u(q2v[0], k2.x, dp4a_u(q2v[1], k2.y,
                           dp4a_u(q2v[2], k2.z, dp4a_u(q2v[3], k2.w, 0u))));
            unsigned dB3 = dp4a_u(q2v[0], k3.x, dp4a_u(q2v[1], k3.y,
                           dp4a_u(q2v[2], k3.z, dp4a_u(q2v[3], k3.w, 0u))));

            float cj0 = s_cj[4 * g + 0], cj1 = s_cj[4 * g + 1];
            float cj2 = s_cj[4 * g + 2], cj3 = s_cj[4 * g + 3];

            float wA0 = ex2_approx(fmaf(__uint_as_float(0x4B000000u | dA0), twoS2, cj0));
            float wA1 = ex2_approx(fmaf(__uint_as_float(0x4B000000u | dA1), twoS2, cj1));
            float wA2 = ex2_approx(fmaf(__uint_as_float(0x4B000000u | dA2), twoS2, cj2));
            float wA3 = ex2_approx(fmaf(__uint_as_float(0x4B000000u | dA3), twoS2, cj3));
            float wB0 = ex2_approx(fmaf(__uint_as_float(0x4B000000u | dB0), twoS2, cj0));
            float wB1 = ex2_approx(fmaf(__uint_as_float(0x4B000000u | dB1), twoS2, cj1));
            float wB2 = ex2_approx(fmaf(__uint_as_float(0x4B000000u | dB2), twoS2, cj2));
            float wB3 = ex2_approx(fmaf(__uint_as_float(0x4B000000u | dB3), twoS2, cj3));

            // wq = round(w*R) = low byte of (w*R + 2^23); wq in [94,255]
            unsigned tA0 = __float_as_uint(fmaf(wA0, R1, 12582912.0f));
            unsigned tA1 = __float_as_uint(fmaf(wA1, R1, 12582912.0f));
            unsigned tA2 = __float_as_uint(fmaf(wA2, R1, 12582912.0f));
            unsigned tA3 = __float_as_uint(fmaf(wA3, R1, 12582912.0f));
            unsigned tB0 = __float_as_uint(fmaf(wB0, R2, 12582912.0f));
            unsigned tB1 = __float_as_uint(fmaf(wB1, R2, 12582912.0f));
            unsigned tB2 = __float_as_uint(fmaf(wB2, R2, 12582912.0f));
            unsigned tB3 = __float_as_uint(fmaf(wB3, R2, 12582912.0f));
            unsigned wv1 = prmt(tA0, tA1, 0x1140u) | prmt(tA2, tA3, 0x4011u);
            unsigned wv2 = prmt(tB0, tB1, 0x1140u) | prmt(tB2, tB3, 0x4011u);

            ds1 = dp4a_u(wv1, 0x01010101u, ds1);
            ds2 = dp4a_u(wv2, 0x01010101u, ds2);

            uint4 p0 = sqT4[4 * g + 0];
            uint4 p1 = sqT4[4 * g + 1];
            uint4 p2 = sqT4[4 * g + 2];
            uint4 p3 = sqT4[4 * g + 3];
            av1[0]  = dp4a_u(wv1, p0.x, av1[0]);   av2[0]  = dp4a_u(wv2, p0.x, av2[0]);
            av1[1]  = dp4a_u(wv1, p0.y, av1[1]);   av2[1]  = dp4a_u(wv2, p0.y, av2[1]);
            av1[2]  = dp4a_u(wv1, p0.z, av1[2]);   av2[2]  = dp4a_u(wv2, p0.z, av2[2]);
            av1[3]  = dp4a_u(wv1, p0.w, av1[3]);   av2[3]  = dp4a_u(wv2, p0.w, av2[3]);
            av1[4]  = dp4a_u(wv1, p1.x, av1[4]);   av2[4]  = dp4a_u(wv2, p1.x, av2[4]);
            av1[5]  = dp4a_u(wv1, p1.y, av1[5]);   av2[5]  = dp4a_u(wv2, p1.y, av2[5]);
            av1[6]  = dp4a_u(wv1, p1.z, av1[6]);   av2[6]  = dp4a_u(wv2, p1.z, av2[6]);
            av1[7]  = dp4a_u(wv1, p1.w, av1[7]);   av2[7]  = dp4a_u(wv2, p1.w, av2[7]);
            av1[8]  = dp4a_u(wv1, p2.x, av1[8]);   av2[8]  = dp4a_u(wv2, p2.x, av2[8]);
            av1[9]  = dp4a_u(wv1, p2.y, av1[9]);   av2[9]  = dp4a_u(wv2, p2.y, av2[9]);
            av1[10] = dp4a_u(wv1, p2.z, av1[10]);  av2[10] = dp4a_u(wv2, p2.z, av2[10]);
            av1[11] = dp4a_u(wv1, p2.w, av1[11]);  av2[11] = dp4a_u(wv2, p2.w, av2[11]);
            av1[12] = dp4a_u(wv1, p3.x, av1[12]);  av2[12] = dp4a_u(wv2, p3.x, av2[12]);
            av1[13] = dp4a_u(wv1, p3.y, av1[13]);  av2[13] = dp4a_u(wv2, p3.y, av2[13]);
            av1[14] = dp4a_u(wv1, p3.z, av1[14]);  av2[14] = dp4a_u(wv2, p3.z, av2[14]);
            av1[15] = dp4a_u(wv1, p3.w, av1[15]);  av2[15] = dp4a_u(wv2, p3.w, av2[15]);
        }

        // write integer partials, component-major (coalesced both ways)
        unsigned* base = g_part + (size_t)((b * JTILES + jt) * 17) * N_;
        #pragma unroll
        for (int d = 0; d < 16; ++d) {
            base[d * N_ + i1] = av1[d];
            base[d * N_ + i2] = av2[d];
        }
        base[16 * N_ + i1] = ds1;
        base[16 * N_ + i2] = ds2;
    }

    // ---- last-block-of-(b,rt) finalize ----
    __syncthreads();
    if (tid == 0) {
        __threadfence();                              // release partial stores
        unsigned old = atomicAdd(&g_cnt[b * ROWTILES + rt], 1u);
        s_last = ((old % (unsigned)JTILES) == (unsigned)(JTILES - 1)) ? 1 : 0;
    }
    __syncthreads();
    if (!s_last) return;
    __threadfence();                                  // acquire peers' stores
    if (!active) return;

    #pragma unroll
    for (int half = 0; half < 2; ++half) {
        int i = (half == 0) ? i1 : i2;
        const unsigned* p0 = g_part + (size_t)(b * JTILES) * 17 * N_ + i;
        unsigned v[17];
        #pragma unroll
        for (int d = 0; d < 17; ++d) v[d] = 0u;
        #pragma unroll
        for (int g = 0; g < 3; ++g) {
            unsigned tmp[6][17];
            #pragma unroll
            for (int jt2 = 0; jt2 < 6; ++jt2) {
                const unsigned* base2 = p0 + (size_t)(g * 6 + jt2) * 17 * N_;
                #pragma unroll
                for (int d = 0; d < 17; ++d) tmp[jt2][d] = __ldcg(&base2[d * N_]);
            }
            #pragma unroll
            for (int d = 0; d < 17; ++d)
                v[d] += ((tmp[0][d] + tmp[1][d]) + (tmp[2][d] + tmp[3][d]))
                      + (tmp[4][d] + tmp[5][d]);
        }

        // out = (sum wq*u / sum wq) * xmax / 255
        float r = xmax / (255.0f * (float)v[16]);
        int by = i / NP_, bx = i - by * NP_;
        float* ob = out + b * (IMG * IMG) + (by * 4) * IMG + bx * 4;
        #pragma unroll
        for (int ky = 0; ky < 4; ++ky) {
            float4 o;
            o.x = (float)v[ky * 4 + 0] * r;
            o.y = (float)v[ky * 4 + 1] * r;
            o.z = (float)v[ky * 4 + 2] * r;
            o.w = (float)v[ky * 4 + 3] * r;
            *reinterpret_cast<float4*>(ob + ky * IMG) = o;
        }
    }
}

extern "C" void kernel_launch(void* const* d_in, const int* in_sizes, int n_in,
                              void* d_out, int out_size) {
    const float* x = (const float*)d_in[0];
    float* out = (float*)d_out;

    k_max<<<MAXBLOCKS, 256>>>(x);
    k_attn<<<ATTN_BLOCKS, 128>>>(x, out);
}

// round 15
// speedup vs baseline: 1.5529x; 1.5529x over previous
#include <cuda_runtime.h>

// Problem constants
#define IMG   144
#define B_    4
#define N_    1296
#define NP_   36
#define KT    9            // key splits
#define KEYS_PER 144       // N_/KT
#define QB    27           // query blocks per batch (48 rows each)
#define QROWS 48
#define NBLK  (B_ * QB * KT)   // 972 blocks x 96 threads (3 warps x 16 queries)
#define MAXBLOCKS 27
#define RSTRIDE 48         // smem token row stride in bytes (24 bf16: 16 dims + ones + pad)

#define LOG2E 1.4426950408889634f

// Scratch: f32 partials [b][kt][d(17)][N_] (~3.2MB, L2-resident); block maxes;
// per-(b,qb) counters (monotone across replays: each launch adds exactly KT,
// old%KT==KT-1 marks last arrival of THIS launch; no reset needed).
__device__ float    g_part[B_ * KT * 17 * N_];
__device__ float    g_bmax[MAXBLOCKS];
__device__ unsigned g_cnt[B_ * QB];

__device__ __forceinline__ float ex2_approx(float a) {
    float r;
    asm("ex2.approx.ftz.f32 %0, %1;" : "=f"(r) : "f"(a));
    return r;
}
// pack two f32 -> bf16x2 {lo, hi}  (PTX: first src -> hi)
__device__ __forceinline__ unsigned bf2(float lo, float hi) {
    unsigned r;
    asm("cvt.rn.bf16x2.f32 %0, %1, %2;" : "=r"(r) : "f"(hi), "f"(lo));
    return r;
}
__device__ __forceinline__ unsigned smaddr(const void* p) {
    return (unsigned)__cvta_generic_to_shared(p);
}
__device__ __forceinline__ void ldsm4(unsigned r[4], unsigned a) {
    asm volatile("ldmatrix.sync.aligned.m8n8.x4.shared.b16 {%0,%1,%2,%3}, [%4];"
        : "=r"(r[0]), "=r"(r[1]), "=r"(r[2]), "=r"(r[3]) : "r"(a));
}
__device__ __forceinline__ void ldsm4t(unsigned r[4], unsigned a) {
    asm volatile("ldmatrix.sync.aligned.m8n8.x4.trans.shared.b16 {%0,%1,%2,%3}, [%4];"
        : "=r"(r[0]), "=r"(r[1]), "=r"(r[2]), "=r"(r[3]) : "r"(a));
}
__device__ __forceinline__ void ldsm2t(unsigned r[2], unsigned a) {
    asm volatile("ldmatrix.sync.aligned.m8n8.x2.trans.shared.b16 {%0,%1}, [%2];"
        : "=r"(r[0]), "=r"(r[1]) : "r"(a));
}
__device__ __forceinline__ void mma16816(float d[4], const unsigned a[4],
                                         unsigned b0, unsigned b1, const float c[4]) {
    asm volatile("mma.sync.aligned.m16n8k16.row.col.f32.bf16.bf16.f32 "
        "{%0,%1,%2,%3}, {%4,%5,%6,%7}, {%8,%9}, {%10,%11,%12,%13};"
        : "=f"(d[0]), "=f"(d[1]), "=f"(d[2]), "=f"(d[3])
        : "r"(a[0]), "r"(a[1]), "r"(a[2]), "r"(a[3]), "r"(b0), "r"(b1),
          "f"(c[0]), "f"(c[1]), "f"(c[2]), "f"(c[3]));
}

// ---------------- kernel 0: per-block max (values >= 0) ----------------
__global__ void k_max(const float* __restrict__ x) {
    const float4* xv = reinterpret_cast<const float4*>(x);
    int base = blockIdx.x * 768 + threadIdx.x;   // 27*768 = 20736 float4 exactly
    float4 v0 = xv[base];
    float4 v1 = xv[base + 256];
    float4 v2 = xv[base + 512];
    float m = fmaxf(fmaxf(fmaxf(v0.x, v0.y), fmaxf(v0.z, v0.w)),
              fmaxf(fmaxf(fmaxf(v1.x, v1.y), fmaxf(v1.z, v1.w)),
                    fmaxf(fmaxf(v2.x, v2.y), fmaxf(v2.z, v2.w))));
    #pragma unroll
    for (int o = 16; o > 0; o >>= 1)
        m = fmaxf(m, __shfl_xor_sync(0xFFFFFFFFu, m, o));
    __shared__ float sm[8];
    int warp = threadIdx.x >> 5, lane = threadIdx.x & 31;
    if (lane == 0) sm[warp] = m;
    __syncthreads();
    if (warp == 0) {
        m = sm[lane & 7];
        #pragma unroll
        for (int o = 4; o > 0; o >>= 1)
            m = fmaxf(m, __shfl_xor_sync(0xFFFFFFFFu, m, o));
        if (lane == 0) g_bmax[blockIdx.x] = m;
    }
}

// ---------------- kernel 1: tensor-core flash attention ---------------------
// Per warp: 16 queries x 144 keys via m16n8k16 bf16 HMMA. The QK accumulator
// fragment IS the A-fragment of PV (classic FA2 register reuse). Tokens carry
// a 17th dim of ones so the softmax denominator is a 3rd PV MMA column,
// bitwise-consistent with the numerator. Scores use raw tokens with
// s = log2e/(16 xmax^2); the row/key norm terms keep arg <= ~0 (exact
// row factor cancels in num/denom). Last block per (b,qb) finalizes.
__global__ void __launch_bounds__(96) k_attn(const float* __restrict__ x,
                                             float* __restrict__ out) {
    __shared__ __align__(16) unsigned char s_t[KEYS_PER * RSTRIDE];  // keys bf16
    __shared__ __align__(16) unsigned char s_q[QROWS * RSTRIDE];     // queries bf16
    __shared__ float s_cj[KEYS_PER];   // -s * |t_j|^2
    __shared__ float s_ci[QROWS];      // -s * |t_i|^2
    __shared__ float s_red[3];
    __shared__ int   s_last;

    int bid = blockIdx.x;
    int kt  = bid % KT;
    int qb  = (bid / KT) % QB;
    int b   = bid / (KT * QB);
    int tid = threadIdx.x;
    int lane = tid & 31, warp = tid >> 5;

    const float* xb = x + b * (N_ * 16);
    int k0 = kt * KEYS_PER;
    int q0 = qb * QROWS;

    // ---- global max -> score scale ----
    float m = (tid < MAXBLOCKS) ? g_bmax[tid] : 0.0f;
    #pragma unroll
    for (int o = 16; o > 0; o >>= 1)
        m = fmaxf(m, __shfl_xor_sync(0xFFFFFFFFu, m, o));
    if (lane == 0) s_red[warp] = m;
    __syncthreads();
    float xmax = fmaxf(fmaxf(s_red[0], s_red[1]), s_red[2]);
    float s    = LOG2E / (16.0f * xmax * xmax);
    float twoS = 2.0f * s;

    // ---- fill bf16 tiles + negated scaled norms ----
    // key rows: tid (all), 96+tid (tid<48); query rows: tid-48 (tid>=48)
    {
        int kr = tid;
        #pragma unroll
        for (int rep = 0; rep < 2; ++rep) {
            if (kr < KEYS_PER) {
                const float4* src = reinterpret_cast<const float4*>(xb + (k0 + kr) * 16);
                float4 v0 = src[0], v1 = src[1], v2 = src[2], v3 = src[3];
                float q = 0.f;
                q = fmaf(v0.x,v0.x,fmaf(v0.y,v0.y,fmaf(v0.z,v0.z,fmaf(v0.w,v0.w,q))));
                q = fmaf(v1.x,v1.x,fmaf(v1.y,v1.y,fmaf(v1.z,v1.z,fmaf(v1.w,v1.w,q))));
                q = fmaf(v2.x,v2.x,fmaf(v2.y,v2.y,fmaf(v2.z,v2.z,fmaf(v2.w,v2.w,q))));
                q = fmaf(v3.x,v3.x,fmaf(v3.y,v3.y,fmaf(v3.z,v3.z,fmaf(v3.w,v3.w,q))));
                s_cj[kr] = -s * q;
                uint4* dst = reinterpret_cast<uint4*>(s_t + kr * RSTRIDE);
                dst[0] = make_uint4(bf2(v0.x,v0.y), bf2(v0.z,v0.w), bf2(v1.x,v1.y), bf2(v1.z,v1.w));
                dst[1] = make_uint4(bf2(v2.x,v2.y), bf2(v2.z,v2.w), bf2(v3.x,v3.y), bf2(v3.z,v3.w));
                dst[2] = make_uint4(0x00003F80u, 0u, 0u, 0u);   // dims 16..23 = {1,0,...}
            }
            kr = (tid < 48) ? (96 + tid) : KEYS_PER;            // second pass rows 96..143
        }
        if (tid >= 48) {
            int qr = tid - 48;
            const float4* src = reinterpret_cast<const float4*>(xb + (q0 + qr) * 16);
            float4 v0 = src[0], v1 = src[1], v2 = src[2], v3 = src[3];
            float q = 0.f;
            q = fmaf(v0.x,v0.x,fmaf(v0.y,v0.y,fmaf(v0.z,v0.z,fmaf(v0.w,v0.w,q))));
            q = fmaf(v1.x,v1.x,fmaf(v1.y,v1.y,fmaf(v1.z,v1.z,fmaf(v1.w,v1.w,q))));
            q = fmaf(v2.x,v2.x,fmaf(v2.y,v2.y,fmaf(v2.z,v2.z,fmaf(v2.w,v2.w,q))));
            q = fmaf(v3.x,v3.x,fmaf(v3.y,v3.y,fmaf(v3.z,v3.z,fmaf(v3.w,v3.w,q))));
            s_ci[qr] = -s * q;
            uint4* dst = reinterpret_cast<uint4*>(s_q + qr * RSTRIDE);
            dst[0] = make_uint4(bf2(v0.x,v0.y), bf2(v0.z,v0.w), bf2(v1.x,v1.y), bf2(v1.z,v1.w));
            dst[1] = make_uint4(bf2(v2.x,v2.y), bf2(v2.z,v2.w), bf2(v3.x,v3.y), bf2(v3.z,v3.w));
        }
    }
    __syncthreads();

    int g = lane >> 2, t = lane & 3;
    unsigned st = smaddr(s_t), sq = smaddr(s_q);

    // Q A-fragment (m16k16): lanes 0-15 rows, 16-31 rows with +16B col offset
    unsigned qa[4];
    ldsm4(qa, sq + (unsigned)((warp * 16 + (lane & 15)) * RSTRIDE + ((lane >> 4) << 4)));

    float nci_lo = s_ci[warp * 16 + g];
    float nci_hi = s_ci[warp * 16 + g + 8];

    // per-lane ldmatrix base addresses (row-within-16-key-tile layouts)
    int rl = lane & 7, sec = lane >> 3;
    unsigned baseK = st + (unsigned)((rl + ((sec & 2) ? 8 : 0)) * RSTRIDE + ((sec & 1) ? 16 : 0));
    unsigned baseV = st + (unsigned)((rl + ((sec & 1) ? 8 : 0)) * RSTRIDE + ((sec & 2) ? 16 : 0));
    unsigned baseD = st + (unsigned)((lane & 15) * RSTRIDE + 32);

    float o0[4] = {0,0,0,0}, o1[4] = {0,0,0,0}, od[4] = {0,0,0,0};
    float zc[4] = {0,0,0,0};

    for (int kb = 0; kb < KEYS_PER; kb += 16) {
        unsigned off = (unsigned)(kb * RSTRIDE);
        unsigned kf[4], vf[4], df[2];
        ldsm4 (kf, baseK + off);   // K B-frags: {n0b0, n0b1, n1b0, n1b1}
        ldsm4t(vf, baseV + off);   // V B-frags: {d0-7 b0,b1, d8-15 b0,b1}
        ldsm2t(df, baseD + off);   // ones-col B-frag (dims 16-23)

        float sA[4], sB[4];
        mma16816(sA, qa, kf[0], kf[1], zc);   // keys kb+0..7
        mma16816(sB, qa, kf[2], kf[3], zc);   // keys kb+8..15

        float2 cjA = *reinterpret_cast<const float2*>(s_cj + kb + 2 * t);
        float2 cjB = *reinterpret_cast<const float2*>(s_cj + kb + 8 + 2 * t);
        float eAx_lo = cjA.x + nci_lo, eAy_lo = cjA.y + nci_lo;
        float eAx_hi = cjA.x + nci_hi, eAy_hi = cjA.y + nci_hi;
        float eBx_lo = cjB.x + nci_lo, eBy_lo = cjB.y + nci_lo;
        float eBx_hi = cjB.x + nci_hi, eBy_hi = cjB.y + nci_hi;

        float w00 = ex2_approx(fmaf(sA[0], twoS, eAx_lo));
        float w01 = ex2_approx(fmaf(sA[1], twoS, eAy_lo));
        float w02 = ex2_approx(fmaf(sA[2], twoS, eAx_hi));
        float w03 = ex2_approx(fmaf(sA[3], twoS, eAy_hi));
        float w10 = ex2_approx(fmaf(sB[0], twoS, eBx_lo));
        float w11 = ex2_approx(fmaf(sB[1], twoS, eBy_lo));
        float w12 = ex2_approx(fmaf(sB[2], twoS, eBx_hi));
        float w13 = ex2_approx(fmaf(sB[3], twoS, eBy_hi));

        // P fragment: QK accum layout == PV A layout
        unsigned pa[4];
        pa[0] = bf2(w00, w01);
        pa[1] = bf2(w02, w03);
        pa[2] = bf2(w10, w11);
        pa[3] = bf2(w12, w13);

        mma16816(o0, pa, vf[0], vf[1], o0);   // dims 0-7
        mma16816(o1, pa, vf[2], vf[3], o1);   // dims 8-15
        mma16816(od, pa, df[0], df[1], od);   // denom (col 16 = ones)
    }

    // ---- write partials ----
    {
        int irow = q0 + warp * 16 + g;
        int irow2 = irow + 8;
        float* base = g_part + (size_t)(b * KT + kt) * 17 * N_;
        base[(2*t)  *N_ + irow]  = o0[0];
        base[(2*t+1)*N_ + irow]  = o0[1];
        base[(2*t+8)*N_ + irow]  = o1[0];
        base[(2*t+9)*N_ + irow]  = o1[1];
        base[(2*t)  *N_ + irow2] = o0[2];
        base[(2*t+1)*N_ + irow2] = o0[3];
        base[(2*t+8)*N_ + irow2] = o1[2];
        base[(2*t+9)*N_ + irow2] = o1[3];
        if (t == 0) {
            base[16*N_ + irow]  = od[0];
            base[16*N_ + irow2] = od[2];
        }
    }

    // ---- last-block-of-(b,qb) finalize ----
    __syncthreads();
    if (tid == 0) {
        __threadfence();
        unsigned old = atomicAdd(&g_cnt[b * QB + qb], 1u);
        s_last = ((old % (unsigned)KT) == (unsigned)(KT - 1)) ? 1 : 0;
    }
    __syncthreads();
    if (!s_last) return;
    __threadfence();
    if (tid >= QROWS) return;

    int i = q0 + tid;
    float v[17];
    #pragma unroll
    for (int d = 0; d < 17; ++d) v[d] = 0.f;
    #pragma unroll
    for (int c = 0; c < 3; ++c) {
        float tmp[3][17];
        #pragma unroll
        for (int k2 = 0; k2 < 3; ++k2) {
            const float* base2 = g_part + (size_t)(b * KT + c * 3 + k2) * 17 * N_ + i;
            #pragma unroll
            for (int d = 0; d < 17; ++d) tmp[k2][d] = __ldcg(&base2[d * N_]);
        }
        #pragma unroll
        for (int d = 0; d < 17; ++d) v[d] += (tmp[0][d] + tmp[1][d]) + tmp[2][d];
    }

    float r = 1.0f / v[16];
    int by = i / NP_, bx = i - by * NP_;
    float* ob = out + b * (IMG * IMG) + (by * 4) * IMG + bx * 4;
    #pragma unroll
    for (int ky = 0; ky < 4; ++ky) {
        float4 o;
        o.x = v[ky * 4 + 0] * r;
        o.y = v[ky * 4 + 1] * r;
        o.z = v[ky * 4 + 2] * r;
        o.w = v[ky * 4 + 3] * r;
        *reinterpret_cast<float4*>(ob + ky * IMG) = o;
    }
}

extern "C" void kernel_launch(void* const* d_in, const int* in_sizes, int n_in,
                              void* d_out, int out_size) {
    const float* x = (const float*)d_in[0];
    float* out = (float*)d_out;

    k_max<<<MAXBLOCKS, 256>>>(x);
    k_attn<<<NBLK, 96>>>(x, out);
}